// round 13
// baseline (speedup 1.0000x reference)
#include <cuda_runtime.h>
#include <math.h>

// ---------------- problem constants ----------------
#define B_   32
#define H_   32
#define W_   32
#define DIN  1024
#define DE   64
#define K_   8192
#define S_   16          // 4x4 grid
#define N_   (B_*S_)     // 512 pooled vectors
#define DEC_SIZE (B_*H_*W_*DIN)   // 33554432

// output layout (concatenated, float32):
// [0, DEC_SIZE) decoded | [DEC_SIZE] perplexity | [+1..+1+K_) counts | [..+N_) indices

// ---------------- device scratch ----------------
__device__ float g_pooled[N_ * DIN];          // 2 MB  pooled delta (mean applied)
__device__ float g_flat[N_ * DE];             // 128 KB encoded vectors
__device__ unsigned long long g_best[N_];     // packed (ordered_dist<<32)|idx
__device__ float g_proj[N_ * DIN];            // 2 MB  quantized @ W_out^T + b_out

// ---------------- f32x2 helpers ----------------
__device__ __forceinline__ unsigned long long fma2(unsigned long long a,
                                                   unsigned long long b,
                                                   unsigned long long c) {
    unsigned long long d;
    asm("fma.rn.f32x2 %0, %1, %2, %3;" : "=l"(d) : "l"(a), "l"(b), "l"(c));
    return d;
}
__device__ __forceinline__ unsigned long long add2(unsigned long long a,
                                                   unsigned long long b) {
    unsigned long long d;
    asm("add.rn.f32x2 %0, %1, %2;" : "=l"(d) : "l"(a), "l"(b));
    return d;
}
__device__ __forceinline__ float2 unpack2(unsigned long long v) {
    float lo, hi;
    asm("mov.b64 {%0,%1}, %2;" : "=f"(lo), "=f"(hi) : "l"(v));
    return make_float2(lo, hi);
}

// ---------------- launch 1: pooled delta (reads 268 MB) + counts zeroing ------------
// grid: 1024 blocks = (b*16+g)*2 + half ; 256 threads = grp(2 pixel halves) x 128 c4
// launch_bounds(256,4): <=64 regs -> 4 CTAs/SM = 32 warps/SM for DRAM latency hiding.
__global__ void __launch_bounds__(256, 4) pool_kernel(const float* __restrict__ t0,
                                                      const float* __restrict__ t1,
                                                      float* out_counts) {
    __shared__ float4 sbuf[128];
    int blk  = blockIdx.x;
    if (blk < 32) out_counts[blk * 256 + threadIdx.x] = 0.0f;

    int half = blk & 1;          // which 512-float half of DIN
    int bg   = blk >> 1;
    int b    = bg >> 4;
    int g    = bg & 15;
    int gh = g >> 2, gw = g & 3;
    int grp = threadIdx.x >> 7;              // 0/1 : pixel halves
    int c4  = half * 128 + (threadIdx.x & 127);

    float4 acc = make_float4(0.f, 0.f, 0.f, 0.f);
    int base_h = gh * 8, base_w = gw * 8;
    int i0 = grp * 32;
    #pragma unroll 4
    for (int i = i0; i < i0 + 32; i++) {
        int hh = base_h + (i >> 3);
        int ww = base_w + (i & 7);
        long off = (((long)(b * H_ + hh) * W_ + ww) * DIN) >> 2;
        float4 a = __ldcs(((const float4*)t1) + off + c4);
        float4 c = __ldcs(((const float4*)t0) + off + c4);
        acc.x += a.x - c.x; acc.y += a.y - c.y;
        acc.z += a.z - c.z; acc.w += a.w - c.w;
    }
    if (grp == 1) sbuf[threadIdx.x & 127] = acc;
    __syncthreads();
    if (grp == 0) {
        float4 o = sbuf[threadIdx.x & 127];
        const float inv = 1.0f / 64.0f;
        acc.x = (acc.x + o.x) * inv; acc.y = (acc.y + o.y) * inv;
        acc.z = (acc.z + o.z) * inv; acc.w = (acc.w + o.w) * inv;
        ((float4*)g_pooled)[bg * 256 + c4] = acc;
    }
}

// ---------------- launch 2: project in  flat = pooled @ W_in^T + b_in ----------------
// grid: 128 blocks (4 n each), 256 threads: thread = (d, n-in-block)
// also seeds g_best sentinels.
__global__ void project_in_kernel(const float* __restrict__ W_in, const float* __restrict__ b_in) {
    __shared__ float sp[4 * DIN];   // 16 KB
    int n0 = blockIdx.x * 4;
    if (threadIdx.x < 4) g_best[n0 + threadIdx.x] = 0xFFFFFFFFFFFFFFFFull;
    for (int i = threadIdx.x; i < 4 * 256; i += 256)
        ((float4*)sp)[i] = ((const float4*)(g_pooled + (long)n0 * DIN))[i];
    __syncthreads();

    int d = threadIdx.x & 63;
    int gp = threadIdx.x >> 6;          // 0..3
    const float4* wr = (const float4*)(W_in + d * DIN);
    const float4* p0 = (const float4*)(sp + gp * DIN);   // broadcast within warp
    float a0 = 0.f, a1 = 0.f, a2 = 0.f, a3 = 0.f;
    #pragma unroll 4
    for (int k = 0; k < 256; k += 4) {
        float4 w0 = wr[k],   v0 = p0[k];
        float4 w1 = wr[k+1], v1 = p0[k+1];
        float4 w2 = wr[k+2], v2 = p0[k+2];
        float4 w3 = wr[k+3], v3 = p0[k+3];
        a0 += w0.x*v0.x + w0.y*v0.y + w0.z*v0.z + w0.w*v0.w;
        a1 += w1.x*v1.x + w1.y*v1.y + w1.z*v1.z + w1.w*v1.w;
        a2 += w2.x*v2.x + w2.y*v2.y + w2.z*v2.z + w2.w*v2.w;
        a3 += w3.x*v3.x + w3.y*v3.y + w3.z*v3.z + w3.w*v3.w;
    }
    g_flat[(n0 + gp) * DE + d] = (a0 + a1) + (a2 + a3) + b_in[d];
}

// ---------------- launch 3: argmin (2 queries/thread, 128 thr, 256 blocks) ------------
// grid: 256 blocks = kt(0..127)*2 + nh(0..1); queries n = nh*256+tid and +128.
__global__ void __launch_bounds__(128) argmin_kernel(const float* __restrict__ codebooks) {
    __shared__ float4 sc[64 * 16];   // 16 KB codebook tile
    __shared__ float  scc[64];       // tile norms
    int nh = blockIdx.x & 1;
    int kt = blockIdx.x >> 1;
    int k0 = kt * 64;

    for (int i = threadIdx.x; i < 64 * 16; i += 128)
        sc[i] = ((const float4*)codebooks)[(long)k0 * 16 + i];
    __syncthreads();
    if (threadIdx.x < 64) {
        const float4* cp = sc + threadIdx.x * 16;
        float s = 0.f;
        #pragma unroll
        for (int i = 0; i < 16; i++) {
            float4 v = cp[i];
            s += v.x*v.x + v.y*v.y + v.z*v.z + v.w*v.w;
        }
        scc[threadIdx.x] = s;
    }
    __syncthreads();

    int n0 = nh * 256 + threadIdx.x;
    int n1 = n0 + 128;
    unsigned long long f0[32], f1[32];
    {
        const ulonglong2* p0 = (const ulonglong2*)(g_flat + n0 * DE);
        const ulonglong2* p1 = (const ulonglong2*)(g_flat + n1 * DE);
        #pragma unroll
        for (int i = 0; i < 16; i++) {
            ulonglong2 v0 = p0[i]; f0[2*i] = v0.x; f0[2*i+1] = v0.y;
            ulonglong2 v1 = p1[i]; f1[2*i] = v1.x; f1[2*i+1] = v1.y;
        }
    }

    float best0 = INFINITY, best1 = INFINITY;
    int bi0 = 0x7FFFFFFF, bi1 = 0x7FFFFFFF;
    #pragma unroll 2
    for (int c = 0; c < 64; c++) {
        const ulonglong2* cp = (const ulonglong2*)(sc + c * 16);
        unsigned long long a0=0ull,a1=0ull,a2=0ull,a3=0ull;
        unsigned long long b0=0ull,b1=0ull,b2=0ull,b3=0ull;
        #pragma unroll
        for (int i = 0; i < 8; i++) {
            ulonglong2 c0 = cp[2*i];
            ulonglong2 c1 = cp[2*i+1];
            a0 = fma2(f0[4*i+0], c0.x, a0);
            a1 = fma2(f0[4*i+1], c0.y, a1);
            a2 = fma2(f0[4*i+2], c1.x, a2);
            a3 = fma2(f0[4*i+3], c1.y, a3);
            b0 = fma2(f1[4*i+0], c0.x, b0);
            b1 = fma2(f1[4*i+1], c0.y, b1);
            b2 = fma2(f1[4*i+2], c1.x, b2);
            b3 = fma2(f1[4*i+3], c1.y, b3);
        }
        a0 = add2(a0, a1); a2 = add2(a2, a3); a0 = add2(a0, a2);
        b0 = add2(b0, b1); b2 = add2(b2, b3); b0 = add2(b0, b2);
        float2 ua = unpack2(a0);
        float2 ub = unpack2(b0);
        float cc = scc[c];
        float d0 = cc - 2.0f * (ua.x + ua.y);
        float d1 = cc - 2.0f * (ub.x + ub.y);
        if (d0 < best0) { best0 = d0; bi0 = k0 + c; }
        if (d1 < best1) { best1 = d1; bi1 = k0 + c; }
    }

    unsigned ou0 = __float_as_uint(best0);
    ou0 = (ou0 & 0x80000000u) ? ~ou0 : (ou0 | 0x80000000u);
    unsigned long long pk0 = (((unsigned long long)ou0) << 32) | (unsigned)bi0;
    if (pk0 < g_best[n0]) atomicMin(&g_best[n0], pk0);
    unsigned ou1 = __float_as_uint(best1);
    ou1 = (ou1 & 0x80000000u) ? ~ou1 : (ou1 | 0x80000000u);
    unsigned long long pk1 = (((unsigned long long)ou1) << 32) | (unsigned)bi1;
    if (pk1 < g_best[n1]) atomicMin(&g_best[n1], pk1);
}

// ---------------- launch 4 (ncu-captured): fused quantize + project_out -------------
// grid: 512 blocks = b*16 + j ; 128 threads (4 warps). 64 channels per block.
// Quant tile (16 n) recomputed per block (4 warps x 4 n); j==0 emits counts+indices.
// 3.46 blocks/SM -> ~14 warps/SM for latency hiding of the quantize prologue chain.
__global__ void __launch_bounds__(128) quant_project_kernel(const float* __restrict__ codebooks,
                                     const float* __restrict__ noise,
                                     const float* __restrict__ W_out,
                                     const float* __restrict__ b_out,
                                     float* out_counts, float* out_indices) {
    __shared__ float sq[S_ * DE];   // 4 KB
    int b = blockIdx.x >> 4;
    int j = blockIdx.x & 15;
    int warp = threadIdx.x >> 5, lane = threadIdx.x & 31;

    // 4 warps x 4 n each = 16 n
    #pragma unroll
    for (int t = 0; t < 4; t++) {
        int nl = warp * 4 + t;
        int n  = b * S_ + nl;
        unsigned idx = (unsigned)(g_best[n] & 0xFFFFFFFFull);
        float fA = g_flat[n * DE + lane];
        float fB = g_flat[n * DE + 32 + lane];
        float cA = codebooks[(long)idx * DE + lane];
        float cB = codebooks[(long)idx * DE + 32 + lane];
        float zA = noise[n * DE + lane];
        float zB = noise[n * DE + 32 + lane];
        float rA = fA - cA, rB = fB - cB;
        float r2 = rA * rA + rB * rB;
        float z2 = zA * zA + zB * zB;
        #pragma unroll
        for (int off = 16; off; off >>= 1) {
            r2 += __shfl_xor_sync(0xFFFFFFFFu, r2, off);
            z2 += __shfl_xor_sync(0xFFFFFFFFu, z2, off);
        }
        float scale = sqrtf(r2) / (sqrtf(z2) + 1e-12f);
        sq[nl * DE + lane]      = fA + scale * zA;
        sq[nl * DE + 32 + lane] = fB + scale * zB;
        if (j == 0 && lane == 0) {
            atomicAdd(out_counts + idx, 1.0f);
            out_indices[n] = (float)idx;
        }
    }
    __syncthreads();

    int cl = threadIdx.x & 63;
    int nh = threadIdx.x >> 6;       // 0/1 -> 8 n each
    int c = j * 64 + cl;
    const float4* wr = (const float4*)(W_out + (long)c * DE);
    float4 w[16];
    #pragma unroll
    for (int i = 0; i < 16; i++) w[i] = wr[i];
    float bo = b_out[c];
    #pragma unroll
    for (int t = 0; t < 8; t++) {
        int n = nh * 8 + t;
        const float4* q = (const float4*)(sq + n * DE);   // broadcast
        float p0 = 0.f, p1 = 0.f;
        #pragma unroll
        for (int i = 0; i < 8; i++) {
            float4 qa = q[2*i], qb = q[2*i+1];
            p0 += qa.x*w[2*i].x + qa.y*w[2*i].y + qa.z*w[2*i].z + qa.w*w[2*i].w;
            p1 += qb.x*w[2*i+1].x + qb.y*w[2*i+1].y + qb.z*w[2*i+1].z + qb.w*w[2*i+1].w;
        }
        g_proj[(long)(b * S_ + n) * DIN + c] = p0 + p1 + bo;
    }
}

// ---------------- launch 5: bilinear upsample + write (128 MB) + perplexity ----------
// grid: 1024 blocks = b*32 + h ; 256 threads. Block 0 also computes perplexity.
__global__ void __launch_bounds__(256, 4) upsample_kernel(float* __restrict__ out,
                                const float* __restrict__ counts, float* out_perp) {
    __shared__ float spp[256];
    int b = blockIdx.x >> 5;
    int h = blockIdx.x & 31;
    int c4 = threadIdx.x;

    if (blockIdx.x == 0) {
        float acc = 0.f;
        for (int i = threadIdx.x; i < K_; i += 256) {
            float c = counts[i];
            if (c > 0.0f) {
                float p = c * (1.0f / (float)N_);
                acc += p * logf(p + 1e-12f);
            }
        }
        spp[threadIdx.x] = acc;
        __syncthreads();
        for (int s = 128; s; s >>= 1) {
            if (threadIdx.x < s) spp[threadIdx.x] += spp[threadIdx.x + s];
            __syncthreads();
        }
        if (threadIdx.x == 0) out_perp[0] = expf(-spp[0]);
    }

    float hs = (h + 0.5f) * 0.125f - 0.5f;
    float jf = floorf(hs);
    float fh = hs - jf;
    int jh0 = (int)jf; if (jh0 < 0) jh0 = 0;
    int jh1 = (int)jf + 1; if (jh1 > 3) jh1 = 3; if (jh1 < 0) jh1 = 0;

    const float4* P = (const float4*)g_proj;
    float4 top[4], bot[4];
    #pragma unroll
    for (int gw = 0; gw < 4; gw++) {
        top[gw] = P[(long)(b * S_ + jh0 * 4 + gw) * 256 + c4];
        bot[gw] = P[(long)(b * S_ + jh1 * 4 + gw) * 256 + c4];
    }

    float4* O = (float4*)out + ((long)(b * H_ + h) * W_) * 256 + c4;
    #pragma unroll 4
    for (int w = 0; w < 32; w++) {
        float ws = (w + 0.5f) * 0.125f - 0.5f;
        float wjf = floorf(ws);
        float fw = ws - wjf;
        int jw0 = (int)wjf; if (jw0 < 0) jw0 = 0;
        int jw1 = (int)wjf + 1; if (jw1 > 3) jw1 = 3; if (jw1 < 0) jw1 = 0;

        float w00 = (1.f - fh) * (1.f - fw);
        float w01 = (1.f - fh) * fw;
        float w10 = fh * (1.f - fw);
        float w11 = fh * fw;

        float4 t0 = top[jw0], t1 = top[jw1], b0 = bot[jw0], b1 = bot[jw1];
        float4 v;
        v.x = w00*t0.x + w01*t1.x + w10*b0.x + w11*b1.x;
        v.y = w00*t0.y + w01*t1.y + w10*b0.y + w11*b1.y;
        v.z = w00*t0.z + w01*t1.z + w10*b0.z + w11*b1.z;
        v.w = w00*t0.w + w01*t1.w + w10*b0.w + w11*b1.w;
        __stcs(O + (long)w * 256, v);
    }
}

// ---------------- launch ----------------
extern "C" void kernel_launch(void* const* d_in, const int* in_sizes, int n_in,
                              void* d_out, int out_size) {
    const float* t0        = (const float*)d_in[0];
    const float* t1        = (const float*)d_in[1];
    const float* noise     = (const float*)d_in[2];
    const float* codebooks = (const float*)d_in[3];
    const float* W_in      = (const float*)d_in[4];
    const float* b_in      = (const float*)d_in[5];
    const float* W_out     = (const float*)d_in[6];
    const float* b_out     = (const float*)d_in[7];

    float* out       = (float*)d_out;
    float* out_perp  = out + DEC_SIZE;
    float* out_cnt   = out + DEC_SIZE + 1;
    float* out_idx   = out + DEC_SIZE + 1 + K_;

    pool_kernel<<<1024, 256>>>(t0, t1, out_cnt);       // 1
    project_in_kernel<<<128, 256>>>(W_in, b_in);       // 2
    argmin_kernel<<<256, 128>>>(codebooks);            // 3
    quant_project_kernel<<<512, 128>>>(codebooks, noise, W_out, b_out, out_cnt, out_idx); // 4 <- ncu
    upsample_kernel<<<B_ * H_, 256>>>(out, out_cnt, out_perp);                            // 5
}

// round 14
// speedup vs baseline: 1.2625x; 1.2625x over previous
#include <cuda_runtime.h>
#include <math.h>

// ---------------- problem constants ----------------
#define B_   32
#define H_   32
#define W_   32
#define DIN  1024
#define DE   64
#define K_   8192
#define S_   16          // 4x4 grid
#define N_   (B_*S_)     // 512 pooled vectors
#define DEC_SIZE (B_*H_*W_*DIN)   // 33554432

// output layout (concatenated, float32):
// [0, DEC_SIZE) decoded | [DEC_SIZE] perplexity | [+1..+1+K_) counts | [..+N_) indices

// ---------------- device scratch ----------------
__device__ float g_pooled[N_ * DIN];          // 2 MB  pooled delta (mean applied)
__device__ float g_flat[N_ * DE];             // 128 KB encoded vectors
__device__ unsigned long long g_best[N_];     // packed (ordered_dist<<32)|idx
__device__ float g_proj[N_ * DIN];            // 2 MB  quantized @ W_out^T + b_out

// ---------------- f32x2 helpers ----------------
__device__ __forceinline__ unsigned long long fma2(unsigned long long a,
                                                   unsigned long long b,
                                                   unsigned long long c) {
    unsigned long long d;
    asm("fma.rn.f32x2 %0, %1, %2, %3;" : "=l"(d) : "l"(a), "l"(b), "l"(c));
    return d;
}
__device__ __forceinline__ unsigned long long add2(unsigned long long a,
                                                   unsigned long long b) {
    unsigned long long d;
    asm("add.rn.f32x2 %0, %1, %2;" : "=l"(d) : "l"(a), "l"(b));
    return d;
}
__device__ __forceinline__ float2 unpack2(unsigned long long v) {
    float lo, hi;
    asm("mov.b64 {%0,%1}, %2;" : "=f"(lo), "=f"(hi) : "l"(v));
    return make_float2(lo, hi);
}

// ---------------- launch 1: pooled delta (reads 268 MB) + counts zeroing ------------
// grid: 1024 blocks = (b*16+g)*2 + half ; 256 threads = grp(2 pixel halves) x 128 c4
__global__ void __launch_bounds__(256, 4) pool_kernel(const float* __restrict__ t0,
                                                      const float* __restrict__ t1,
                                                      float* out_counts) {
    __shared__ float4 sbuf[128];
    int blk  = blockIdx.x;
    if (blk < 32) out_counts[blk * 256 + threadIdx.x] = 0.0f;

    int half = blk & 1;          // which 512-float half of DIN
    int bg   = blk >> 1;
    int b    = bg >> 4;
    int g    = bg & 15;
    int gh = g >> 2, gw = g & 3;
    int grp = threadIdx.x >> 7;              // 0/1 : pixel halves
    int c4  = half * 128 + (threadIdx.x & 127);

    float4 acc = make_float4(0.f, 0.f, 0.f, 0.f);
    int base_h = gh * 8, base_w = gw * 8;
    int i0 = grp * 32;
    #pragma unroll 4
    for (int i = i0; i < i0 + 32; i++) {
        int hh = base_h + (i >> 3);
        int ww = base_w + (i & 7);
        long off = (((long)(b * H_ + hh) * W_ + ww) * DIN) >> 2;
        float4 a = __ldcs(((const float4*)t1) + off + c4);
        float4 c = __ldcs(((const float4*)t0) + off + c4);
        acc.x += a.x - c.x; acc.y += a.y - c.y;
        acc.z += a.z - c.z; acc.w += a.w - c.w;
    }
    if (grp == 1) sbuf[threadIdx.x & 127] = acc;
    __syncthreads();
    if (grp == 0) {
        float4 o = sbuf[threadIdx.x & 127];
        const float inv = 1.0f / 64.0f;
        acc.x = (acc.x + o.x) * inv; acc.y = (acc.y + o.y) * inv;
        acc.z = (acc.z + o.z) * inv; acc.w = (acc.w + o.w) * inv;
        ((float4*)g_pooled)[bg * 256 + c4] = acc;
    }
}

// ---------------- launch 2: project in  flat = pooled @ W_in^T + b_in ----------------
// grid: 128 blocks (4 n each), 256 threads (8 warps).
// Warp-per-output-channel: lanes split k -> W reads are COALESCED (4 lines/instr,
// not 32), LDS reads conflict-free. 4 n accumulated per warp, shfl-reduced.
__global__ void project_in_kernel(const float* __restrict__ W_in, const float* __restrict__ b_in) {
    __shared__ float sp[4 * DIN];   // 16 KB staged pooled rows
    int n0 = blockIdx.x * 4;
    if (threadIdx.x < 4) g_best[n0 + threadIdx.x] = 0xFFFFFFFFFFFFFFFFull;
    for (int i = threadIdx.x; i < 4 * 256; i += 256)
        ((float4*)sp)[i] = ((const float4*)(g_pooled + (long)n0 * DIN))[i];
    __syncthreads();

    int warp = threadIdx.x >> 5, lane = threadIdx.x & 31;
    const float4* sp4 = (const float4*)sp;
    #pragma unroll
    for (int d = warp; d < DE; d += 8) {
        const float4* wr = (const float4*)(W_in + (long)d * DIN);
        float a0 = 0.f, a1 = 0.f, a2 = 0.f, a3 = 0.f;
        #pragma unroll
        for (int it = 0; it < 8; it++) {
            int k4 = it * 32 + lane;           // float4 index 0..255, coalesced
            float4 w  = wr[k4];
            float4 p0 = sp4[k4];
            float4 p1 = sp4[256 + k4];
            float4 p2 = sp4[512 + k4];
            float4 p3 = sp4[768 + k4];
            a0 += w.x*p0.x + w.y*p0.y + w.z*p0.z + w.w*p0.w;
            a1 += w.x*p1.x + w.y*p1.y + w.z*p1.z + w.w*p1.w;
            a2 += w.x*p2.x + w.y*p2.y + w.z*p2.z + w.w*p2.w;
            a3 += w.x*p3.x + w.y*p3.y + w.z*p3.z + w.w*p3.w;
        }
        #pragma unroll
        for (int off = 16; off; off >>= 1) {
            a0 += __shfl_xor_sync(0xFFFFFFFFu, a0, off);
            a1 += __shfl_xor_sync(0xFFFFFFFFu, a1, off);
            a2 += __shfl_xor_sync(0xFFFFFFFFu, a2, off);
            a3 += __shfl_xor_sync(0xFFFFFFFFu, a3, off);
        }
        if (lane == 0) {
            float bb = b_in[d];
            g_flat[(n0 + 0) * DE + d] = a0 + bb;
            g_flat[(n0 + 1) * DE + d] = a1 + bb;
            g_flat[(n0 + 2) * DE + d] = a2 + bb;
            g_flat[(n0 + 3) * DE + d] = a3 + bb;
        }
    }
}

// ---------------- launch 3: argmin (2 queries/thread, 128 thr, 256 blocks) ------------
// grid: 256 blocks = kt(0..127)*2 + nh(0..1); queries n = nh*256+tid and +128.
__global__ void __launch_bounds__(128) argmin_kernel(const float* __restrict__ codebooks) {
    __shared__ float4 sc[64 * 16];   // 16 KB codebook tile
    __shared__ float  scc[64];       // tile norms
    int nh = blockIdx.x & 1;
    int kt = blockIdx.x >> 1;
    int k0 = kt * 64;

    for (int i = threadIdx.x; i < 64 * 16; i += 128)
        sc[i] = ((const float4*)codebooks)[(long)k0 * 16 + i];
    __syncthreads();
    if (threadIdx.x < 64) {
        const float4* cp = sc + threadIdx.x * 16;
        float s = 0.f;
        #pragma unroll
        for (int i = 0; i < 16; i++) {
            float4 v = cp[i];
            s += v.x*v.x + v.y*v.y + v.z*v.z + v.w*v.w;
        }
        scc[threadIdx.x] = s;
    }
    __syncthreads();

    int n0 = nh * 256 + threadIdx.x;
    int n1 = n0 + 128;
    unsigned long long f0[32], f1[32];
    {
        const ulonglong2* p0 = (const ulonglong2*)(g_flat + n0 * DE);
        const ulonglong2* p1 = (const ulonglong2*)(g_flat + n1 * DE);
        #pragma unroll
        for (int i = 0; i < 16; i++) {
            ulonglong2 v0 = p0[i]; f0[2*i] = v0.x; f0[2*i+1] = v0.y;
            ulonglong2 v1 = p1[i]; f1[2*i] = v1.x; f1[2*i+1] = v1.y;
        }
    }

    float best0 = INFINITY, best1 = INFINITY;
    int bi0 = 0x7FFFFFFF, bi1 = 0x7FFFFFFF;
    #pragma unroll 2
    for (int c = 0; c < 64; c++) {
        const ulonglong2* cp = (const ulonglong2*)(sc + c * 16);
        unsigned long long a0=0ull,a1=0ull,a2=0ull,a3=0ull;
        unsigned long long b0=0ull,b1=0ull,b2=0ull,b3=0ull;
        #pragma unroll
        for (int i = 0; i < 8; i++) {
            ulonglong2 c0 = cp[2*i];
            ulonglong2 c1 = cp[2*i+1];
            a0 = fma2(f0[4*i+0], c0.x, a0);
            a1 = fma2(f0[4*i+1], c0.y, a1);
            a2 = fma2(f0[4*i+2], c1.x, a2);
            a3 = fma2(f0[4*i+3], c1.y, a3);
            b0 = fma2(f1[4*i+0], c0.x, b0);
            b1 = fma2(f1[4*i+1], c0.y, b1);
            b2 = fma2(f1[4*i+2], c1.x, b2);
            b3 = fma2(f1[4*i+3], c1.y, b3);
        }
        a0 = add2(a0, a1); a2 = add2(a2, a3); a0 = add2(a0, a2);
        b0 = add2(b0, b1); b2 = add2(b2, b3); b0 = add2(b0, b2);
        float2 ua = unpack2(a0);
        float2 ub = unpack2(b0);
        float cc = scc[c];
        float d0 = cc - 2.0f * (ua.x + ua.y);
        float d1 = cc - 2.0f * (ub.x + ub.y);
        if (d0 < best0) { best0 = d0; bi0 = k0 + c; }
        if (d1 < best1) { best1 = d1; bi1 = k0 + c; }
    }

    unsigned ou0 = __float_as_uint(best0);
    ou0 = (ou0 & 0x80000000u) ? ~ou0 : (ou0 | 0x80000000u);
    unsigned long long pk0 = (((unsigned long long)ou0) << 32) | (unsigned)bi0;
    if (pk0 < g_best[n0]) atomicMin(&g_best[n0], pk0);
    unsigned ou1 = __float_as_uint(best1);
    ou1 = (ou1 & 0x80000000u) ? ~ou1 : (ou1 | 0x80000000u);
    unsigned long long pk1 = (((unsigned long long)ou1) << 32) | (unsigned)bi1;
    if (pk1 < g_best[n1]) atomicMin(&g_best[n1], pk1);
}

// ---------------- launch 4 (ncu-captured): fused quantize + project_out -------------
// grid: 128 blocks = b*4 + j ; 256 threads.  (R12 configuration: measured 10.9us)
__global__ void quant_project_kernel(const float* __restrict__ codebooks,
                                     const float* __restrict__ noise,
                                     const float* __restrict__ W_out,
                                     const float* __restrict__ b_out,
                                     float* out_counts, float* out_indices) {
    __shared__ float sq[S_ * DE];   // 4 KB
    int b = blockIdx.x >> 2;
    int j = blockIdx.x & 3;
    int warp = threadIdx.x >> 5, lane = threadIdx.x & 31;

    // 8 warps x 2 n each = 16 n
    #pragma unroll
    for (int t = 0; t < 2; t++) {
        int nl = warp * 2 + t;
        int n  = b * S_ + nl;
        unsigned idx = (unsigned)(g_best[n] & 0xFFFFFFFFull);
        float fA = g_flat[n * DE + lane];
        float fB = g_flat[n * DE + 32 + lane];
        float cA = codebooks[(long)idx * DE + lane];
        float cB = codebooks[(long)idx * DE + 32 + lane];
        float zA = noise[n * DE + lane];
        float zB = noise[n * DE + 32 + lane];
        float rA = fA - cA, rB = fB - cB;
        float r2 = rA * rA + rB * rB;
        float z2 = zA * zA + zB * zB;
        #pragma unroll
        for (int off = 16; off; off >>= 1) {
            r2 += __shfl_xor_sync(0xFFFFFFFFu, r2, off);
            z2 += __shfl_xor_sync(0xFFFFFFFFu, z2, off);
        }
        float scale = sqrtf(r2) / (sqrtf(z2) + 1e-12f);
        sq[nl * DE + lane]      = fA + scale * zA;
        sq[nl * DE + 32 + lane] = fB + scale * zB;
        if (j == 0 && lane == 0) {
            atomicAdd(out_counts + idx, 1.0f);
            out_indices[n] = (float)idx;
        }
    }
    __syncthreads();

    int c = j * 256 + threadIdx.x;
    const float4* wr = (const float4*)(W_out + (long)c * DE);
    float4 w[16];
    #pragma unroll
    for (int i = 0; i < 16; i++) w[i] = wr[i];
    float bo = b_out[c];
    #pragma unroll 2
    for (int n = 0; n < S_; n++) {
        const float4* q = (const float4*)(sq + n * DE);   // broadcast
        float acc = bo;
        #pragma unroll
        for (int i = 0; i < 16; i++) {
            float4 qq = q[i];
            acc += qq.x*w[i].x + qq.y*w[i].y + qq.z*w[i].z + qq.w*w[i].w;
        }
        g_proj[(long)(b * S_ + n) * DIN + c] = acc;
    }
}

// ---------------- launch 5: bilinear upsample + write (128 MB) + perplexity ----------
// grid: 1024 blocks = b*32 + h ; 256 threads. Block 0 also computes perplexity.
__global__ void __launch_bounds__(256, 4) upsample_kernel(float* __restrict__ out,
                                const float* __restrict__ counts, float* out_perp) {
    __shared__ float spp[256];
    int b = blockIdx.x >> 5;
    int h = blockIdx.x & 31;
    int c4 = threadIdx.x;

    if (blockIdx.x == 0) {
        float acc = 0.f;
        for (int i = threadIdx.x; i < K_; i += 256) {
            float c = counts[i];
            if (c > 0.0f) {
                float p = c * (1.0f / (float)N_);
                acc += p * logf(p + 1e-12f);
            }
        }
        spp[threadIdx.x] = acc;
        __syncthreads();
        for (int s = 128; s; s >>= 1) {
            if (threadIdx.x < s) spp[threadIdx.x] += spp[threadIdx.x + s];
            __syncthreads();
        }
        if (threadIdx.x == 0) out_perp[0] = expf(-spp[0]);
    }

    float hs = (h + 0.5f) * 0.125f - 0.5f;
    float jf = floorf(hs);
    float fh = hs - jf;
    int jh0 = (int)jf; if (jh0 < 0) jh0 = 0;
    int jh1 = (int)jf + 1; if (jh1 > 3) jh1 = 3; if (jh1 < 0) jh1 = 0;

    const float4* P = (const float4*)g_proj;
    float4 top[4], bot[4];
    #pragma unroll
    for (int gw = 0; gw < 4; gw++) {
        top[gw] = P[(long)(b * S_ + jh0 * 4 + gw) * 256 + c4];
        bot[gw] = P[(long)(b * S_ + jh1 * 4 + gw) * 256 + c4];
    }

    float4* O = (float4*)out + ((long)(b * H_ + h) * W_) * 256 + c4;
    #pragma unroll 4
    for (int w = 0; w < 32; w++) {
        float ws = (w + 0.5f) * 0.125f - 0.5f;
        float wjf = floorf(ws);
        float fw = ws - wjf;
        int jw0 = (int)wjf; if (jw0 < 0) jw0 = 0;
        int jw1 = (int)wjf + 1; if (jw1 > 3) jw1 = 3; if (jw1 < 0) jw1 = 0;

        float w00 = (1.f - fh) * (1.f - fw);
        float w01 = (1.f - fh) * fw;
        float w10 = fh * (1.f - fw);
        float w11 = fh * fw;

        float4 t0 = top[jw0], t1 = top[jw1], b0 = bot[jw0], b1 = bot[jw1];
        float4 v;
        v.x = w00*t0.x + w01*t1.x + w10*b0.x + w11*b1.x;
        v.y = w00*t0.y + w01*t1.y + w10*b0.y + w11*b1.y;
        v.z = w00*t0.z + w01*t1.z + w10*b0.z + w11*b1.z;
        v.w = w00*t0.w + w01*t1.w + w10*b0.w + w11*b1.w;
        __stcs(O + (long)w * 256, v);
    }
}

// ---------------- launch ----------------
extern "C" void kernel_launch(void* const* d_in, const int* in_sizes, int n_in,
                              void* d_out, int out_size) {
    const float* t0        = (const float*)d_in[0];
    const float* t1        = (const float*)d_in[1];
    const float* noise     = (const float*)d_in[2];
    const float* codebooks = (const float*)d_in[3];
    const float* W_in      = (const float*)d_in[4];
    const float* b_in      = (const float*)d_in[5];
    const float* W_out     = (const float*)d_in[6];
    const float* b_out     = (const float*)d_in[7];

    float* out       = (float*)d_out;
    float* out_perp  = out + DEC_SIZE;
    float* out_cnt   = out + DEC_SIZE + 1;
    float* out_idx   = out + DEC_SIZE + 1 + K_;

    pool_kernel<<<1024, 256>>>(t0, t1, out_cnt);       // 1
    project_in_kernel<<<128, 256>>>(W_in, b_in);       // 2
    argmin_kernel<<<256, 128>>>(codebooks);            // 3
    quant_project_kernel<<<128, 256>>>(codebooks, noise, W_out, b_out, out_cnt, out_idx); // 4 <- ncu
    upsample_kernel<<<B_ * H_, 256>>>(out, out_cnt, out_perp);                            // 5
}